// round 2
// baseline (speedup 1.0000x reference)
#include <cuda_runtime.h>
#include <cuda_bf16.h>

#define FEAT_N 2
#define FEAT_C 512
#define FEAT_H 100
#define FEAT_W 152
#define NUM_ROIS 512
#define AH 14
#define AW 14
#define SPATIAL_SCALE 0.0625f
#define CH_CHUNK 8          // channels per block
#define CHUNKS_PER_ROI (FEAT_C / CH_CHUNK)   // 64
#define BINS (AH * AW)      // 196

// 5 blocks/SM * 196 thr -> ptxas reg budget ~64: enough to hold all 32
// prefetched corner values in registers (MLP=32 per thread).
__global__ __launch_bounds__(BINS, 5) void roi_align_kernel(
    const float* __restrict__ feat,
    const float* __restrict__ rois,
    float* __restrict__ out)
{
    const int r      = blockIdx.x >> 6;          // / CHUNKS_PER_ROI
    const int chunk  = blockIdx.x & (CHUNKS_PER_ROI - 1);
    const int c0     = chunk * CH_CHUNK;

    const int tid = threadIdx.x;                 // 0..195
    const int ph  = tid / AW;
    const int pw  = tid - ph * AW;

    const float* rp = rois + r * 5;
    const int   b       = (int)rp[0];
    const float x_start = rp[1] * SPATIAL_SCALE;
    const float y_start = rp[2] * SPATIAL_SCALE;
    const float x_end   = rp[3] * SPATIAL_SCALE;
    const float y_end   = rp[4] * SPATIAL_SCALE;

    const float roi_w = fmaxf(x_end - x_start, 0.0f);
    const float roi_h = fmaxf(y_end - y_start, 0.0f);
    const float bin_h = roi_h * (1.0f / (float)(AH - 1));
    const float bin_w = roi_w * (1.0f / (float)(AW - 1));

    float ys = y_start + (float)ph * bin_h;
    float xs = x_start + (float)pw * bin_w;
    ys = fminf(fmaxf(ys, 0.0f), (float)(FEAT_H - 1));
    xs = fminf(fmaxf(xs, 0.0f), (float)(FEAT_W - 1));

    const int y0 = (int)floorf(ys);
    const int x0 = (int)floorf(xs);
    const int y1 = min(y0 + 1, FEAT_H - 1);
    const int x1 = min(x0 + 1, FEAT_W - 1);
    const float wy = ys - (float)y0;
    const float wx = xs - (float)x0;

    const float w00 = (1.0f - wy) * (1.0f - wx);
    const float w01 = (1.0f - wy) * wx;
    const float w10 = wy * (1.0f - wx);
    const float w11 = wy * wx;

    const int o00 = y0 * FEAT_W + x0;
    const int o01 = y0 * FEAT_W + x1;
    const int o10 = y1 * FEAT_W + x0;
    const int o11 = y1 * FEAT_W + x1;

    const int HW = FEAT_H * FEAT_W;
    const float* f = feat + ((size_t)b * FEAT_C + c0) * HW;
    float* op = out + ((size_t)r * FEAT_C + c0) * BINS + tid;

    // Phase 1: issue ALL corner loads (32 independent LDGs in flight)
    float v00[CH_CHUNK], v01[CH_CHUNK], v10[CH_CHUNK], v11[CH_CHUNK];
    #pragma unroll
    for (int cc = 0; cc < CH_CHUNK; cc++) {
        const float* fp = f + cc * HW;
        v00[cc] = __ldg(fp + o00);
        v01[cc] = __ldg(fp + o01);
        v10[cc] = __ldg(fp + o10);
        v11[cc] = __ldg(fp + o11);
    }

    // Phase 2: combine + coalesced stores
    #pragma unroll
    for (int cc = 0; cc < CH_CHUNK; cc++) {
        float v = w00 * v00[cc];
        v = fmaf(w01, v01[cc], v);
        v = fmaf(w10, v10[cc], v);
        v = fmaf(w11, v11[cc], v);
        op[cc * BINS] = v;
    }
}

extern "C" void kernel_launch(void* const* d_in, const int* in_sizes, int n_in,
                              void* d_out, int out_size)
{
    const float* feat = (const float*)d_in[0];
    const float* rois = (const float*)d_in[1];
    float* out = (float*)d_out;

    dim3 grid(NUM_ROIS * CHUNKS_PER_ROI);
    dim3 block(BINS);
    roi_align_kernel<<<grid, block>>>(feat, rois, out);
}

// round 3
// speedup vs baseline: 1.5822x; 1.5822x over previous
#include <cuda_runtime.h>
#include <cuda_bf16.h>

#define FEAT_N 2
#define FEAT_C 512
#define FEAT_H 100
#define FEAT_W 152
#define NUM_ROIS 512
#define AH 14
#define AW 14
#define SPATIAL_SCALE 0.0625f
#define CH_CHUNK 16         // channels per block
#define CHUNKS_PER_ROI (FEAT_C / CH_CHUNK)   // 32
#define BINS (AH * AW)      // 196

// 7 blocks/SM cap -> ~41 regs: enough for a rolling depth-2 prefetch
// (8 live values) WITHOUT spilling, while keeping occupancy ~76%.
__global__ __launch_bounds__(BINS, 7) void roi_align_kernel(
    const float* __restrict__ feat,
    const float* __restrict__ rois,
    float* __restrict__ out)
{
    const int r      = blockIdx.x >> 5;          // / CHUNKS_PER_ROI
    const int chunk  = blockIdx.x & (CHUNKS_PER_ROI - 1);
    const int c0     = chunk * CH_CHUNK;

    const int tid = threadIdx.x;                 // 0..195
    const int ph  = tid / AW;
    const int pw  = tid - ph * AW;

    const float* rp = rois + r * 5;
    const int   b       = (int)rp[0];
    const float x_start = rp[1] * SPATIAL_SCALE;
    const float y_start = rp[2] * SPATIAL_SCALE;
    const float x_end   = rp[3] * SPATIAL_SCALE;
    const float y_end   = rp[4] * SPATIAL_SCALE;

    const float roi_w = fmaxf(x_end - x_start, 0.0f);
    const float roi_h = fmaxf(y_end - y_start, 0.0f);
    const float bin_h = roi_h * (1.0f / (float)(AH - 1));
    const float bin_w = roi_w * (1.0f / (float)(AW - 1));

    float ys = y_start + (float)ph * bin_h;
    float xs = x_start + (float)pw * bin_w;
    ys = fminf(fmaxf(ys, 0.0f), (float)(FEAT_H - 1));
    xs = fminf(fmaxf(xs, 0.0f), (float)(FEAT_W - 1));

    const int y0 = (int)floorf(ys);
    const int x0 = (int)floorf(xs);
    const int y1 = min(y0 + 1, FEAT_H - 1);
    const int x1 = min(x0 + 1, FEAT_W - 1);
    const float wy = ys - (float)y0;
    const float wx = xs - (float)x0;

    const float w00 = (1.0f - wy) * (1.0f - wx);
    const float w01 = (1.0f - wy) * wx;
    const float w10 = wy * (1.0f - wx);
    const float w11 = wy * wx;

    const int o00 = y0 * FEAT_W + x0;
    const int o01 = y0 * FEAT_W + x1;
    const int o10 = y1 * FEAT_W + x0;
    const int o11 = y1 * FEAT_W + x1;

    const int HW = FEAT_H * FEAT_W;
    const float* p = feat + ((size_t)b * FEAT_C + c0) * HW;
    float* op = out + ((size_t)r * FEAT_C + c0) * BINS + tid;

    // Rolling depth-2 software pipeline: only 8 value regs live at once.
    float a00 = __ldg(p + o00);
    float a01 = __ldg(p + o01);
    float a10 = __ldg(p + o10);
    float a11 = __ldg(p + o11);

    #pragma unroll
    for (int cc = 0; cc < CH_CHUNK; cc++) {
        const float* pn = p + HW;
        float b00, b01, b10, b11;
        if (cc < CH_CHUNK - 1) {
            b00 = __ldg(pn + o00);
            b01 = __ldg(pn + o01);
            b10 = __ldg(pn + o10);
            b11 = __ldg(pn + o11);
        }
        float v = w00 * a00;
        v = fmaf(w01, a01, v);
        v = fmaf(w10, a10, v);
        v = fmaf(w11, a11, v);
        op[cc * BINS] = v;
        if (cc < CH_CHUNK - 1) {
            a00 = b00; a01 = b01; a10 = b10; a11 = b11;
            p = pn;
        }
    }
}

extern "C" void kernel_launch(void* const* d_in, const int* in_sizes, int n_in,
                              void* d_out, int out_size)
{
    const float* feat = (const float*)d_in[0];
    const float* rois = (const float*)d_in[1];
    float* out = (float*)d_out;

    dim3 grid(NUM_ROIS * CHUNKS_PER_ROI);
    dim3 block(BINS);
    roi_align_kernel<<<grid, block>>>(feat, rois, out);
}

// round 4
// speedup vs baseline: 1.5902x; 1.0051x over previous
#include <cuda_runtime.h>
#include <cuda_bf16.h>

#define FEAT_N 2
#define FEAT_C 512
#define FEAT_H 100
#define FEAT_W 152
#define NUM_ROIS 512
#define AH 14
#define AW 14
#define SPATIAL_SCALE 0.0625f
#define CH_CHUNK 8          // channels per block
#define CHUNKS_PER_ROI (FEAT_C / CH_CHUNK)   // 64
#define BINS (AH * AW)      // 196

// 6 blocks/SM -> 42 warps (66% occ), reg cap 48. Inner loop processes TWO
// channels per iteration with 8 independent NAMED scalar loads (no arrays ->
// no spill; no rotation -> no serial chain). #pragma unroll lets ptxas
// overlap load batches across iterations for MLP ~8-16.
__global__ __launch_bounds__(BINS, 6) void roi_align_kernel(
    const float* __restrict__ feat,
    const float* __restrict__ rois,
    float* __restrict__ out)
{
    const int r      = blockIdx.x >> 6;          // / CHUNKS_PER_ROI
    const int chunk  = blockIdx.x & (CHUNKS_PER_ROI - 1);
    const int c0     = chunk * CH_CHUNK;

    const int tid = threadIdx.x;                 // 0..195
    const int ph  = tid / AW;
    const int pw  = tid - ph * AW;

    const float* rp = rois + r * 5;
    const int   b       = (int)rp[0];
    const float x_start = rp[1] * SPATIAL_SCALE;
    const float y_start = rp[2] * SPATIAL_SCALE;
    const float x_end   = rp[3] * SPATIAL_SCALE;
    const float y_end   = rp[4] * SPATIAL_SCALE;

    const float roi_w = fmaxf(x_end - x_start, 0.0f);
    const float roi_h = fmaxf(y_end - y_start, 0.0f);
    const float bin_h = roi_h * (1.0f / (float)(AH - 1));
    const float bin_w = roi_w * (1.0f / (float)(AW - 1));

    float ys = y_start + (float)ph * bin_h;
    float xs = x_start + (float)pw * bin_w;
    ys = fminf(fmaxf(ys, 0.0f), (float)(FEAT_H - 1));
    xs = fminf(fmaxf(xs, 0.0f), (float)(FEAT_W - 1));

    const int y0 = (int)floorf(ys);
    const int x0 = (int)floorf(xs);
    const int y1 = min(y0 + 1, FEAT_H - 1);
    const int x1 = min(x0 + 1, FEAT_W - 1);
    const float wy = ys - (float)y0;
    const float wx = xs - (float)x0;

    const float w00 = (1.0f - wy) * (1.0f - wx);
    const float w01 = (1.0f - wy) * wx;
    const float w10 = wy * (1.0f - wx);
    const float w11 = wy * wx;

    const int o00 = y0 * FEAT_W + x0;
    const int o01 = y0 * FEAT_W + x1;
    const int o10 = y1 * FEAT_W + x0;
    const int o11 = y1 * FEAT_W + x1;

    const int HW = FEAT_H * FEAT_W;
    const float* f = feat + ((size_t)b * FEAT_C + c0) * HW;
    float* op = out + ((size_t)r * FEAT_C + c0) * BINS + tid;

    #pragma unroll
    for (int cc = 0; cc < CH_CHUNK; cc += 2) {
        const float* fa = f + cc * HW;
        const float* fb = fa + HW;
        // 8 independent loads, all named scalars
        float a00 = __ldg(fa + o00);
        float a01 = __ldg(fa + o01);
        float a10 = __ldg(fa + o10);
        float a11 = __ldg(fa + o11);
        float b00 = __ldg(fb + o00);
        float b01 = __ldg(fb + o01);
        float b10 = __ldg(fb + o10);
        float b11 = __ldg(fb + o11);

        float va = w00 * a00;
        va = fmaf(w01, a01, va);
        va = fmaf(w10, a10, va);
        va = fmaf(w11, a11, va);

        float vb = w00 * b00;
        vb = fmaf(w01, b01, vb);
        vb = fmaf(w10, b10, vb);
        vb = fmaf(w11, b11, vb);

        op[cc * BINS]       = va;
        op[(cc + 1) * BINS] = vb;
    }
}

extern "C" void kernel_launch(void* const* d_in, const int* in_sizes, int n_in,
                              void* d_out, int out_size)
{
    const float* feat = (const float*)d_in[0];
    const float* rois = (const float*)d_in[1];
    float* out = (float*)d_out;

    dim3 grid(NUM_ROIS * CHUNKS_PER_ROI);
    dim3 block(BINS);
    roi_align_kernel<<<grid, block>>>(feat, rois, out);
}